// round 1
// baseline (speedup 1.0000x reference)
#include <cuda_runtime.h>
#include <math_constants.h>

#define B_   32
#define N_   128
#define C_   25
#define NC   3200                       // N_*C_ candidates per center
#define S_   13107200                   // B_*N_*N_*C_ elements per output tensor
#define CAP  128
#define RAD2 64.0f
#define EPS2 1e-4f

// Canonical distance^2: used for BOTH selection and output so the keep mask is
// self-consistent bit-for-bit. dvec = pos[j] - pos[i] + off[c].
__device__ __forceinline__ float d2_canonical(float pix, float piy, float piz,
                                              float pjx, float pjy, float pjz,
                                              float ox,  float oy,  float oz) {
    float dx = __fadd_rn(__fsub_rn(pjx, pix), ox);
    float dy = __fadd_rn(__fsub_rn(pjy, piy), oy);
    float dz = __fadd_rn(__fsub_rn(pjz, piz), oz);
    return __fmaf_rn(dx, dx, __fmaf_rn(dy, dy, __fmul_rn(dz, dz)));
}

__global__ void zero_counts_kernel(float* __restrict__ out) {
    if (threadIdx.x < B_) out[(size_t)3 * S_ + threadIdx.x] = 0.0f;
}

__global__ __launch_bounds__(256)
void pbc_graph_kernel(const float* __restrict__ pos,
                      const float* __restrict__ cell,
                      float* __restrict__ out) {
    const int center = blockIdx.x;       // b*128 + i
    const int b = center >> 7;
    const int i = center & 127;
    const int tid = threadIdx.x;

    __shared__ float spos[N_ * 3];
    __shared__ float soff[C_ * 3];
    __shared__ float sdist[NC];
    __shared__ int   swcnt[8];
    __shared__ int   s_n;
    __shared__ unsigned long long slist[CAP];
    __shared__ unsigned long long s_T;

    // load positions of this image's atoms
    for (int t = tid; t < N_ * 3; t += 256) spos[t] = pos[(size_t)b * N_ * 3 + t];

    // periodic offsets: off[c,k] = u0*cell[b,0,k] + u1*cell[b,1,k], u2 = 0
    if (tid < C_ * 3) {
        int c = tid / 3, k = tid - c * 3;
        float u0 = (float)(c / 5 - 2);
        float u1 = (float)(c % 5 - 2);
        soff[tid] = __fmaf_rn(u0, cell[b * 9 + k], __fmul_rn(u1, cell[b * 9 + 3 + k]));
    }
    if (tid == 0) { s_n = 0; s_T = ~0ULL; }
    __syncthreads();

    const float pix = spos[i * 3 + 0];
    const float piy = spos[i * 3 + 1];
    const float piz = spos[i * 3 + 2];

    // ---- phase 1: compute d2 for all 3200 candidates, count within ----
    int local_within = 0;
#pragma unroll
    for (int s = 0; s < 13; s++) {
        int cand = tid + 256 * s;
        if (cand < NC) {
            int j = cand / 25;
            int c = cand - j * 25;
            float d2 = d2_canonical(pix, piy, piz,
                                    spos[j * 3], spos[j * 3 + 1], spos[j * 3 + 2],
                                    soff[c * 3], soff[c * 3 + 1], soff[c * 3 + 2]);
            bool within = (d2 <= RAD2) && (d2 > EPS2);
            sdist[cand] = within ? d2 : CUDART_INF_F;
            local_within += within ? 1 : 0;
        }
    }
    int wsum = __reduce_add_sync(0xffffffffu, local_within);
    if ((tid & 31) == 0) swcnt[tid >> 5] = wsum;
    __syncthreads();
    int cntw = 0;
#pragma unroll
    for (int q = 0; q < 8; q++) cntw += swcnt[q];     // uniform across block

    // ---- phase 2: exact 32nd-smallest key via value bisection + small-bin rank ----
    if (cntw > 32) {
        float lo = 0.0f, hi = RAD2;
        int cnt_lo = 0, cnt_hi = cntw;
        for (int iter = 0; iter < 48; iter++) {
            if (cnt_hi - cnt_lo <= CAP) break;
            float mid = 0.5f * (lo + hi);
            if (!(mid > lo && mid < hi)) break;       // float exhaustion guard
            int lc = 0;
#pragma unroll
            for (int s = 0; s < 13; s++) {
                int cand = tid + 256 * s;
                if (cand < NC) lc += (sdist[cand] <= mid) ? 1 : 0;
            }
            int ws = __reduce_add_sync(0xffffffffu, lc);
            __syncthreads();                          // protect swcnt reuse
            if ((tid & 31) == 0) swcnt[tid >> 5] = ws;
            __syncthreads();
            int cm = 0;
#pragma unroll
            for (int q = 0; q < 8; q++) cm += swcnt[q];
            if (cm >= 32) { hi = mid; cnt_hi = cm; }
            else          { lo = mid; cnt_lo = cm; }
        }

        // compact candidates with d2 in (lo, hi]
#pragma unroll
        for (int s = 0; s < 13; s++) {
            int cand = tid + 256 * s;
            if (cand < NC) {
                float d = sdist[cand];
                if (d > lo && d <= hi) {
                    int p = atomicAdd(&s_n, 1);
                    if (p < CAP)
                        slist[p] = ((unsigned long long)__float_as_uint(d) << 12)
                                 | (unsigned)cand;
                }
            }
        }
        __syncthreads();
        int n = min(s_n, CAP);
        int need = 32 - cnt_lo;                       // in [1, 32]
        if (tid < n) {
            unsigned long long k = slist[tid];
            int r = 0;
            for (int m = 0; m < n; m++) r += (slist[m] < k) ? 1 : 0;
            if (r == need - 1) s_T = k;               // exact 32nd smallest key
        }
        __syncthreads();
    }

    const unsigned long long T = s_T;
    const size_t base = (size_t)center * NC;

    // ---- phase 3: write outputs (store-bound) ----
#pragma unroll
    for (int s = 0; s < 13; s++) {
        int cand = tid + 256 * s;
        if (cand < NC) {
            float d = sdist[cand];
            bool within = (d <= RAD2);                // inf sentinel fails this
            unsigned long long key = ((unsigned long long)__float_as_uint(d) << 12)
                                   | (unsigned)cand;
            bool keep = within && (key <= T);
            float dist = 0.0f, ctf = 0.0f, mk = 0.0f;
            if (keep) {
                dist = sqrtf(d);
                int c = cand % 25;
                ctf = (float)(5 * (c / 5 + c % 5));   // (u+rep)·[5,5,1] linearization
                mk = 1.0f;
            }
            out[base + cand]                   = dist;
            out[(size_t)S_ + base + cand]      = ctf;
            out[(size_t)2 * S_ + base + cand]  = mk;
        }
    }

    if (tid == 0)
        atomicAdd(&out[(size_t)3 * S_ + b], (float)(cntw < 32 ? cntw : 32));
}

extern "C" void kernel_launch(void* const* d_in, const int* in_sizes, int n_in,
                              void* d_out, int out_size) {
    const float* pos;
    const float* cell;
    if (n_in >= 2 && in_sizes[0] == B_ * N_ * 3) {
        pos  = (const float*)d_in[0];
        cell = (const float*)d_in[1];
    } else {
        pos  = (const float*)d_in[1];
        cell = (const float*)d_in[0];
    }
    float* out = (float*)d_out;

    zero_counts_kernel<<<1, 32>>>(out);
    pbc_graph_kernel<<<B_ * N_, 256>>>(pos, cell, out);
}